// round 12
// baseline (speedup 1.0000x reference)
#include <cuda_runtime.h>
#include <stdint.h>

#define BB 4
#define NP 8192
#define NG 8192
#define T  128
#define WPB (T / 32)                 // 4 warps per block
#define Q  8                         // queries per lane
#define QG 256                       // queries per warp-task (32 lanes x Q)
#define NQG (NP / QG)                // 32 query groups per batch
#define ASL 32                       // acc point-slices (over compacted gt pairs)
#define CSL 64                       // com point-slices (4096 pred pairs / 64 = 64 pairs each)
#define CSLP (NP / 2 / CSL)          // 64 pairs per com slice
#define NTA (BB * NQG * ASL)         // 4096 acc warp-tasks
#define NTC (BB * NQG * CSL)         // 8192 com warp-tasks
#define NTASK (NTA + NTC)            // 12288
#define NBLK 740                     // 5 CTAs/SM x 148 SMs, all co-resident
#define NWARP (NBLK * WPB)           // 2960 warps

#define INF_BITS 0x7F800000u

// ---------------- device scratch (no allocs; counters self-reset per replay) ----------------
// pair-interleaved packed layout: for point pair (2p, 2p+1):
//   entry[2p]   = { (x0,x1), (y0,y1) }
//   entry[2p+1] = { (z0,z1), (sq0,sq1) }
__device__ ulonglong2 g_pkgt[BB][NG];  // compacted valid gt (prefilled {0,0,0,inf} each replay)
__device__ ulonglong2 g_pkpr[BB][NP];  // all pred points
__device__ int      g_gtidx[BB][NG];   // original gt index of compacted entry
__device__ int      g_cnt[BB];
__device__ unsigned g_prmin[BB * NP];  // per-pred min d2 (float bits)
__device__ unsigned g_gtmin[BB * NG];  // per-ORIGINAL-gt min d2 (float bits)
__device__ int      g_bad;             // 1 => gt_valid is 1-byte bool; 0 => int32
__device__ int      g_bar1, g_bar2;    // grid barrier counters
__device__ int      g_done;            // completion counter

// ---------------- packed f32x2 helpers ----------------
__device__ __forceinline__ unsigned long long f2pk(float lo, float hi) {
    unsigned long long r;
    asm("mov.b64 %0, {%1,%2};" : "=l"(r) : "f"(lo), "f"(hi));
    return r;
}
__device__ __forceinline__ unsigned long long fma2(unsigned long long a, unsigned long long b,
                                                   unsigned long long c) {
    unsigned long long r;
    asm("fma.rn.f32x2 %0, %1, %2, %3;" : "=l"(r) : "l"(a), "l"(b), "l"(c));
    return r;
}
__device__ __forceinline__ void upk(unsigned long long v, float& lo, float& hi) {
    asm("mov.b64 {%0,%1}, %2;" : "=f"(lo), "=f"(hi) : "l"(v));
}

// Grid barrier: safe because all NBLK blocks are co-resident
// (__launch_bounds__(128,5): regs<=102, smem tiny).
__device__ __forceinline__ void grid_barrier(int* ctr) {
    __syncthreads();
    if (threadIdx.x == 0) {
        __threadfence();
        atomicAdd(ctr, 1);
        while (atomicAdd(ctr, 0) < NBLK) __nanosleep(64);
        __threadfence();
    }
    __syncthreads();
}

// One warp-autonomous Chamfer task: 256 queries vs one point-slice.
// No shared memory, no block sync. Tile points read as lane-uniform LDG.128.
template <bool IS_ACC>
__device__ __forceinline__ void do_task(int t, const float* __restrict__ pr, int lane) {
    // t = (b * NQG + qg) * NSL + sl
    int sl, qg, b;
    if (IS_ACC) { sl = t & (ASL - 1); int r = t >> 5; qg = r & (NQG - 1); b = r >> 5; }
    else        { sl = t & (CSL - 1); int r = t >> 6; qg = r & (NQG - 1); b = r >> 5; }
    int cnt = g_cnt[b];
    int qbase = qg * QG;

    int p0, p1;
    if (IS_ACC) {
        int npp = (cnt + 1) >> 1;               // pairs of compacted gt
        int Lp = (npp + ASL - 1) / ASL;         // pairs per slice
        p0 = sl * Lp;
        p1 = min(p0 + Lp, npp);
        if (p0 >= p1) return;
    } else {
        if (qbase >= cnt) return;               // whole task's queries invalid
        p0 = sl * CSLP;
        p1 = p0 + CSLP;
    }

    const ulonglong2* __restrict__ pk = IS_ACC ? g_pkgt[b] : g_pkpr[b];

    unsigned long long q2x[Q], q2y[Q], q2z[Q];
    float qsq[Q], m0[Q], m1[Q];
#pragma unroll
    for (int q = 0; q < Q; q++) {
        int qq = qbase + q * 32 + lane;
        float x, y, z, sq;
        if (IS_ACC) {
            const float* p = pr + ((size_t)b * NP + qq) * 3;
            x = p[0]; y = p[1]; z = p[2];
            sq = x * x + y * y + z * z;
        } else {
            // read query from packed gt (garbage beyond cnt: result discarded)
            const float* f = reinterpret_cast<const float*>(&g_pkgt[b][0]);
            int e = (qq >> 1) * 8 + (qq & 1);
            x = f[e]; y = f[e + 2]; z = f[e + 4]; sq = f[e + 6];
        }
        float nx = -2.f * x, ny = -2.f * y, nz = -2.f * z;
        q2x[q] = f2pk(nx, nx); q2y[q] = f2pk(ny, ny); q2z[q] = f2pk(nz, nz);
        qsq[q] = sq;
        m0[q] = __uint_as_float(INF_BITS);
        m1[q] = __uint_as_float(INF_BITS);
    }

#pragma unroll 2
    for (int p2 = p0; p2 < p1; p2++) {
        ulonglong2 v1 = pk[2 * p2];       // (x0,x1),(y0,y1)  lane-uniform LDG.128
        ulonglong2 v2 = pk[2 * p2 + 1];   // (z0,z1),(sq0,sq1)
#pragma unroll
        for (int q = 0; q < Q; q++) {
            unsigned long long t2 = fma2(q2x[q], v1.x, fma2(q2y[q], v1.y, fma2(q2z[q], v2.x, v2.y)));
            float tl, th; upk(t2, tl, th);
            m0[q] = fminf(m0[q], tl);
            m1[q] = fminf(m1[q], th);
        }
    }

#pragma unroll
    for (int q = 0; q < Q; q++) {
        int qq = qbase + q * 32 + lane;
        float m = fmaxf(fminf(m0[q], m1[q]) + qsq[q], 0.f);
        if (IS_ACC) {
            atomicMin(&g_prmin[b * NP + qq], __float_as_uint(m));
        } else if (qq < cnt) {
            int orig = g_gtidx[b][qq];
            atomicMin(&g_gtmin[b * NG + orig], __float_as_uint(m));
        }
    }
}

// ---------------- the single persistent kernel ----------------
__global__ void __launch_bounds__(T, 5) k_all(const float* __restrict__ pr,
                                              const float* __restrict__ gt,
                                              const void* __restrict__ valid,
                                              float* __restrict__ out) {
    int tid = threadIdx.x;
    int gtid = blockIdx.x * T + tid;
    int gstride = NBLK * T;   // 94720 threads

    // ======== Phase A: resets + build packed pred + prefill packed gt + detect ========
    for (int k = gtid; k < BB * NP; k += gstride) g_prmin[k] = INF_BITS;
    for (int k = gtid; k < BB * NG; k += gstride) g_gtmin[k] = INF_BITS;

    // build pair-interleaved pred (com tiles)
    for (int i2 = gtid; i2 < BB * (NP / 2); i2 += gstride) {
        int b = i2 >> 12;                 // / (NP/2)
        int p2 = i2 & (NP / 2 - 1);
        const float* p = pr + ((size_t)b * NP + p2 * 2) * 3;
        float x0 = p[0], y0 = p[1], z0 = p[2];
        float x1 = p[3], y1 = p[4], z1 = p[5];
        float s0 = x0 * x0 + y0 * y0 + z0 * z0;
        float s1 = x1 * x1 + y1 * y1 + z1 * z1;
        ulonglong2 e0, e1;
        e0.x = f2pk(x0, x1); e0.y = f2pk(y0, y1);
        e1.x = f2pk(z0, z1); e1.y = f2pk(s0, s1);
        g_pkpr[b][2 * p2] = e0;
        g_pkpr[b][2 * p2 + 1] = e1;
    }
    // prefill packed gt with sentinel {0,0,0,+inf} (pad safety; Phase B overwrites [0,cnt))
    {
        float finf = __uint_as_float(INF_BITS);
        unsigned long long ZZ = f2pk(0.f, 0.f), II = f2pk(finf, finf);
        ulonglong2 eZ, eI;
        eZ.x = ZZ; eZ.y = ZZ;
        eI.x = ZZ; eI.y = II;
        for (int i2 = gtid; i2 < BB * (NG / 2); i2 += gstride) {
            int b = i2 >> 12;
            int p2 = i2 & (NG / 2 - 1);
            g_pkgt[b][2 * p2] = eZ;
            g_pkgt[b][2 * p2 + 1] = eI;
        }
    }
    // detect: read only (BB*NG)/4 words, safe under both layouts
    {
        const unsigned* w = (const unsigned*)valid;
        int found = 0;
        for (int k = gtid; k < (BB * NG) / 4; k += gstride)
            if (w[k] > 1u) found = 1;
        if (found) g_bad = 1;
    }
    grid_barrier(&g_bar1);

    // ======== Phase B: warp-aggregated compaction into packed gt ========
    if (gtid < BB * NG) {
        int fmt_byte = g_bad;
        int b = gtid >> 13;
        int g = gtid & (NG - 1);
        bool v;
        if (fmt_byte)
            v = (reinterpret_cast<const unsigned char*>(valid)[gtid] != 0);
        else
            v = (reinterpret_cast<const int*>(valid)[gtid] != 0);

        unsigned mask = __ballot_sync(0xffffffffu, v);
        int lane = tid & 31;
        int base = 0;
        if (lane == 0 && mask) base = atomicAdd(&g_cnt[b], __popc(mask));
        base = __shfl_sync(0xffffffffu, base, 0);
        if (v) {
            int p = base + __popc(mask & ((1u << lane) - 1u));
            const float* sgt = gt + (size_t)gtid * 3;
            float x = sgt[0], y = sgt[1], z = sgt[2];
            float sq = x * x + y * y + z * z;
            float* f = reinterpret_cast<float*>(&g_pkgt[b][0]);
            int e = (p >> 1) * 8 + (p & 1);
            f[e] = x; f[e + 2] = y; f[e + 4] = z; f[e + 6] = sq;
            g_gtidx[b][p] = g;
        }
    }
    grid_barrier(&g_bar2);

    // ======== Phase C: warp-autonomous static task loop (NO block sync) ========
    {
        int w = blockIdx.x * WPB + (tid >> 5);
        int lane = tid & 31;
        for (int t = w; t < NTASK; t += NWARP) {
            if (t < NTA) do_task<true>(t, pr, lane);
            else         do_task<false>(t - NTA, pr, lane);
        }
    }

    // ======== Phase D: last block reduces + resets counters ========
    __shared__ bool isLast;
    __shared__ float sa;
    __shared__ float sc[BB];
    __threadfence();
    __syncthreads();
    if (tid == 0) {
        int prev = atomicAdd(&g_done, 1);
        isLast = (prev == NBLK - 1);
        if (isLast) __threadfence();
        sa = 0.f;
    }
    if (tid < BB) sc[tid] = 0.f;
    __syncthreads();
    if (!isLast) return;

    float la = 0.f;
    for (int i = tid; i < BB * NP; i += T)
        la += __uint_as_float(g_prmin[i]);
    atomicAdd(&sa, la);

    for (int bb = 0; bb < BB; bb++) {
        float lc = 0.f;
        for (int i = tid; i < NG; i += T) {
            unsigned v = g_gtmin[bb * NG + i];
            if (v != INF_BITS) lc += __uint_as_float(v);
        }
        atomicAdd(&sc[bb], lc);
    }
    __syncthreads();

    if (tid == 0) {
        float loss_acc = sa / (float)(BB * NP);
        float loss_com = 0.f;
        for (int bb = 0; bb < BB; bb++)
            loss_com += sc[bb] / fmaxf((float)g_cnt[bb], 1.f);
        loss_com /= (float)BB;
        out[0] = 2.f * (loss_acc + loss_com);  // acc + com + cd, cd = acc + com

        for (int bb = 0; bb < BB; bb++) g_cnt[bb] = 0;
        g_bad = 0; g_bar1 = 0; g_bar2 = 0; g_done = 0;
    }
}

// ---------------- launch ----------------
extern "C" void kernel_launch(void* const* d_in, const int* in_sizes, int n_in,
                              void* d_out, int out_size) {
    const float* pr    = (const float*)d_in[0];  // [B,NP,3] f32
    const float* gt    = (const float*)d_in[1];  // [B,NG,3] f32
    const void*  valid = d_in[2];                // [B,NG] bool(1B) or int32

    k_all<<<NBLK, T>>>(pr, gt, valid, (float*)d_out);
}